// round 2
// baseline (speedup 1.0000x reference)
#include <cuda_runtime.h>
#include <math.h>

#define BATCH 8
#define CIN   512
#define COUT  256
#define SDIM  512
#define HW    64

// scratch (allocation-free rule: __device__ globals)
__device__ float g_s[BATCH * CIN];                 // style modulation  [b][ci]
__device__ float g_wsq[COUT * CIN];                // sum_k w^2         [co][ci]
__device__ float g_demod[BATCH * COUT];            // scale*demod       [b][co]
__device__ float g_wp[4 * 9 * CIN * COUT];         // phase weights [phase][tap][ci][co]

// ---------------------------------------------------------------------------
// s[b,ci] = style[b,:] . (mod_weight[ci,:] * mod_scale) + mod_bias[ci]
// one warp per (b,ci)
// ---------------------------------------------------------------------------
__global__ void k_style(const float* __restrict__ style,
                        const float* __restrict__ mw,
                        const float* __restrict__ mb) {
    int idx  = blockIdx.x * 8 + (threadIdx.x >> 5);   // 4096 warps
    int lane = threadIdx.x & 31;
    int b  = idx / CIN;
    int ci = idx - b * CIN;
    const float* st = style + b * SDIM;
    const float* w  = mw + ci * SDIM;
    float acc = 0.f;
    for (int d = lane; d < SDIM; d += 32) acc += st[d] * w[d];
#pragma unroll
    for (int o = 16; o; o >>= 1) acc += __shfl_xor_sync(0xffffffffu, acc, o);
    const float mod_scale = 0.044194173824159216f;    // 1/sqrt(512)
    if (lane == 0) g_s[idx] = acc * mod_scale + mb[ci];
}

// ---------------------------------------------------------------------------
// Per (co,ci): wsq and the 4 phase 3x3 kernels from the combined 6x6 kernel
// C[a,b] = sum_{p,q} w[p,q] g[a-2+p] g[b-2+q],   g = [1,3,3,1]/4
// phase (r,c), tap (dy,dx):  P = C[2*dy+3-r, 2*dx+3-c],  dy,dx in {-1,0,1}
// ---------------------------------------------------------------------------
__global__ void k_wprep(const float* __restrict__ weight) {
    int t = blockIdx.x * blockDim.x + threadIdx.x;    // 131072 threads
    int co = t & (COUT - 1);
    int ci = t >> 8;                                  // t / 256
    const float* wp = weight + (co * CIN + ci) * 9;
    float w[3][3];
    float wsq = 0.f;
#pragma unroll
    for (int p = 0; p < 3; ++p)
#pragma unroll
        for (int q = 0; q < 3; ++q) {
            float v = wp[p * 3 + q];
            w[p][q] = v;
            wsq += v * v;
        }
    g_wsq[co * CIN + ci] = wsq;

    const float gv[4] = {0.25f, 0.75f, 0.75f, 0.25f};
    float C[6][6];
#pragma unroll
    for (int a = 0; a < 6; ++a)
#pragma unroll
        for (int bb = 0; bb < 6; ++bb) {
            float acc = 0.f;
#pragma unroll
            for (int p = 0; p < 3; ++p) {
                int ia = a - 2 + p;
                if (ia < 0 || ia > 3) continue;
#pragma unroll
                for (int q = 0; q < 3; ++q) {
                    int ib = bb - 2 + q;
                    if (ib < 0 || ib > 3) continue;
                    acc += w[p][q] * gv[ia] * gv[ib];
                }
            }
            C[a][bb] = acc;
        }

#pragma unroll
    for (int r = 0; r < 2; ++r)
#pragma unroll
        for (int c = 0; c < 2; ++c) {
            int phase = r * 2 + c;
#pragma unroll
            for (int dyi = 0; dyi < 3; ++dyi)
#pragma unroll
                for (int dxi = 0; dxi < 3; ++dxi) {
                    int tap = dyi * 3 + dxi;
                    int a = 2 * dyi + 1 - r;          // 2*(dyi-1)+3-r
                    int bcol = 2 * dxi + 1 - c;
                    g_wp[((phase * 9 + tap) * CIN + ci) * COUT + co] = C[a][bcol];
                }
        }
}

// ---------------------------------------------------------------------------
// demod[b,co] = scale * rsqrt(scale^2 * sum_ci s[b,ci]^2 * wsq[co,ci] + 1e-8)
// one warp per (b,co)
// ---------------------------------------------------------------------------
__global__ void k_demod() {
    int idx  = blockIdx.x * 8 + (threadIdx.x >> 5);   // 2048 warps
    int lane = threadIdx.x & 31;
    int b  = idx / COUT;
    int co = idx - b * COUT;
    float acc = 0.f;
    for (int ci = lane; ci < CIN; ci += 32) {
        float sv = g_s[b * CIN + ci];
        acc += sv * sv * g_wsq[co * CIN + ci];
    }
#pragma unroll
    for (int o = 16; o; o >>= 1) acc += __shfl_xor_sync(0xffffffffu, acc, o);
    const float scale  = 0.014731391274719738f;       // 1/sqrt(512*9)
    const float scale2 = 2.1701388888888888e-4f;      // 1/4608
    if (lane == 0) g_demod[idx] = scale * rsqrtf(scale2 * acc + 1e-8f);
}

// ---------------------------------------------------------------------------
// Main fused conv: one phase per blockIdx.z; 128 co x (8x8 phase-grid px) tile.
// out[b,co,2Y+r,2X+c] = m(b,co) * sum_{ci,tap} xs(b,ci,Y+dy,X+dx) * Wp
// ---------------------------------------------------------------------------
__global__ void __launch_bounds__(256) k_conv(const float* __restrict__ x,
                                              float* __restrict__ out) {
    const int phase = blockIdx.z;
    const int r = phase >> 1, c = phase & 1;
    const int b    = blockIdx.x >> 6;
    const int tile = blockIdx.x & 63;
    const int Y0 = (tile >> 3) * 8;
    const int X0 = (tile & 7) * 8;
    const int co0 = blockIdx.y * 128;

    const int tid = threadIdx.x;
    const int cog = tid >> 4;            // 0..15  -> 8 co each
    const int pxg = tid & 15;            // 0..15  -> 4 px each (row Yl, quad Xq)
    const int Yl = pxg >> 1;
    const int Xq = (pxg & 1) * 4;

    __shared__ float xs[16][10][12];     // [ci][y][x], x rows Y0-1..Y0+8, cols X0-1..X0+8
    __shared__ float ws[16][128];        // [ci][co]

    float acc[8][4];
#pragma unroll
    for (int i = 0; i < 8; ++i)
#pragma unroll
        for (int j = 0; j < 4; ++j) acc[i][j] = 0.f;

    for (int ch = 0; ch < CIN; ch += 16) {
        __syncthreads();
        // load x tile (modulated by s)
        for (int idx = tid; idx < 1600; idx += 256) {
            int k   = idx / 100;
            int rem = idx - k * 100;
            int yy  = rem / 10;
            int xx  = rem - yy * 10;
            int gy = Y0 - 1 + yy;
            int gx = X0 - 1 + xx;
            float v = 0.f;
            if ((unsigned)gy < 64u && (unsigned)gx < 64u)
                v = x[((b * CIN + ch + k) * HW + gy) * HW + gx] * g_s[b * CIN + ch + k];
            xs[k][yy][xx] = v;
        }

        for (int tap = 0; tap < 9; ++tap) {
            __syncthreads();
            const float* wg = g_wp + ((phase * 9 + tap) * CIN + ch) * COUT + co0;
            for (int idx = tid; idx < 2048; idx += 256) {
                int k  = idx >> 7;
                int co = idx & 127;
                ws[k][co] = wg[k * COUT + co];
            }
            __syncthreads();

            const int dyi = tap / 3;
            const int dxi = tap - dyi * 3;
            const int yrow = Yl + dyi;
            const int xcol = Xq + dxi;
#pragma unroll
            for (int k = 0; k < 16; ++k) {
                float xv[4];
#pragma unroll
                for (int j = 0; j < 4; ++j) xv[j] = xs[k][yrow][xcol + j];
#pragma unroll
                for (int i = 0; i < 8; ++i) {
                    float wv = ws[k][cog * 8 + i];
#pragma unroll
                    for (int j = 0; j < 4; ++j)
                        acc[i][j] = fmaf(wv, xv[j], acc[i][j]);
                }
            }
        }
    }

    // epilogue: multiply by scale*demod, write strided phase outputs
    const int Yg = Y0 + Yl;
    const int oy = 2 * Yg + r;
#pragma unroll
    for (int i = 0; i < 8; ++i) {
        int co = co0 + cog * 8 + i;
        float m = g_demod[b * COUT + co];
        float* op = out + ((size_t)(b * COUT + co) * 128 + oy) * 128;
#pragma unroll
        for (int j = 0; j < 4; ++j) {
            int ox = 2 * (X0 + Xq + j) + c;
            op[ox] = acc[i][j] * m;
        }
    }
}

// ---------------------------------------------------------------------------
extern "C" void kernel_launch(void* const* d_in, const int* in_sizes, int n_in,
                              void* d_out, int out_size) {
    const float* x          = (const float*)d_in[0];   // [8,512,64,64]
    const float* style      = (const float*)d_in[1];   // [8,512]
    const float* weight     = (const float*)d_in[2];   // [1,256,512,3,3]
    const float* mod_weight = (const float*)d_in[3];   // [512,512]
    const float* mod_bias   = (const float*)d_in[4];   // [512]
    float* out = (float*)d_out;                        // [8,256,128,128]

    k_style<<<512, 256>>>(style, mod_weight, mod_bias);
    k_wprep<<<512, 256>>>(weight);
    k_demod<<<256, 256>>>();
    dim3 grid(512, 2, 4);
    k_conv<<<grid, 256>>>(x, out);
}

// round 3
// speedup vs baseline: 1.0009x; 1.0009x over previous
#include <cuda_runtime.h>
#include <math.h>

#define BATCH 8
#define CIN   512
#define COUT  256
#define SDIM  512
#define HW    64

// scratch (allocation-free rule: __device__ globals)
__device__ float g_s[BATCH * CIN];                 // style modulation  [b][ci]
__device__ float g_wsq[COUT * CIN];                // sum_k w^2         [co][ci]
__device__ float g_demod[BATCH * COUT];            // scale*demod       [b][co]
__device__ float g_wp[4 * 9 * CIN * COUT];         // phase weights [phase][tap][ci][co]

// ---------------------------------------------------------------------------
// s[b,ci] = style[b,:] . (mod_weight[ci,:] * mod_scale) + mod_bias[ci]
// one warp per (b,ci)
// ---------------------------------------------------------------------------
__global__ void k_style(const float* __restrict__ style,
                        const float* __restrict__ mw,
                        const float* __restrict__ mb) {
    int idx  = blockIdx.x * 8 + (threadIdx.x >> 5);   // 4096 warps
    int lane = threadIdx.x & 31;
    int b  = idx / CIN;
    int ci = idx - b * CIN;
    const float* st = style + b * SDIM;
    const float* w  = mw + ci * SDIM;
    float acc = 0.f;
    for (int d = lane; d < SDIM; d += 32) acc += st[d] * w[d];
#pragma unroll
    for (int o = 16; o; o >>= 1) acc += __shfl_xor_sync(0xffffffffu, acc, o);
    const float mod_scale = 0.044194173824159216f;    // 1/sqrt(512)
    if (lane == 0) g_s[idx] = acc * mod_scale + mb[ci];
}

// ---------------------------------------------------------------------------
// Per (co,ci): wsq and the 4 phase 3x3 kernels from the combined 6x6 kernel
// C[a,b] = sum_{p,q} w[p,q] g[a-2+p] g[b-2+q],   g = [1,3,3,1]/4
// phase (r,c), tap (dy,dx):  P = C[2*dy+3-r, 2*dx+3-c],  dy,dx in {-1,0,1}
// ---------------------------------------------------------------------------
__global__ void k_wprep(const float* __restrict__ weight) {
    int t = blockIdx.x * blockDim.x + threadIdx.x;    // 131072 threads
    int co = t & (COUT - 1);
    int ci = t >> 8;                                  // t / 256
    const float* wp = weight + (co * CIN + ci) * 9;
    float w[3][3];
    float wsq = 0.f;
#pragma unroll
    for (int p = 0; p < 3; ++p)
#pragma unroll
        for (int q = 0; q < 3; ++q) {
            float v = wp[p * 3 + q];
            w[p][q] = v;
            wsq += v * v;
        }
    g_wsq[co * CIN + ci] = wsq;

    const float gv[4] = {0.25f, 0.75f, 0.75f, 0.25f};
    float C[6][6];
#pragma unroll
    for (int a = 0; a < 6; ++a)
#pragma unroll
        for (int bb = 0; bb < 6; ++bb) {
            float acc = 0.f;
#pragma unroll
            for (int p = 0; p < 3; ++p) {
                int ia = a - 2 + p;
                if (ia < 0 || ia > 3) continue;
#pragma unroll
                for (int q = 0; q < 3; ++q) {
                    int ib = bb - 2 + q;
                    if (ib < 0 || ib > 3) continue;
                    acc += w[p][q] * gv[ia] * gv[ib];
                }
            }
            C[a][bb] = acc;
        }

#pragma unroll
    for (int r = 0; r < 2; ++r)
#pragma unroll
        for (int c = 0; c < 2; ++c) {
            int phase = r * 2 + c;
#pragma unroll
            for (int dyi = 0; dyi < 3; ++dyi)
#pragma unroll
                for (int dxi = 0; dxi < 3; ++dxi) {
                    int tap = dyi * 3 + dxi;
                    int a = 2 * dyi + 1 - r;          // 2*(dyi-1)+3-r
                    int bcol = 2 * dxi + 1 - c;
                    g_wp[((phase * 9 + tap) * CIN + ci) * COUT + co] = C[a][bcol];
                }
        }
}

// ---------------------------------------------------------------------------
// demod[b,co] = scale * rsqrt(scale^2 * sum_ci s[b,ci]^2 * wsq[co,ci] + 1e-8)
// one warp per (b,co)
// ---------------------------------------------------------------------------
__global__ void k_demod() {
    int idx  = blockIdx.x * 8 + (threadIdx.x >> 5);   // 2048 warps
    int lane = threadIdx.x & 31;
    int b  = idx / COUT;
    int co = idx - b * COUT;
    float acc = 0.f;
    for (int ci = lane; ci < CIN; ci += 32) {
        float sv = g_s[b * CIN + ci];
        acc += sv * sv * g_wsq[co * CIN + ci];
    }
#pragma unroll
    for (int o = 16; o; o >>= 1) acc += __shfl_xor_sync(0xffffffffu, acc, o);
    const float scale  = 0.014731391274719738f;       // 1/sqrt(512*9)
    const float scale2 = 2.1701388888888888e-4f;      // 1/4608
    if (lane == 0) g_demod[idx] = scale * rsqrtf(scale2 * acc + 1e-8f);
}

// ---------------------------------------------------------------------------
// Main fused conv: one phase per blockIdx.z; 128 co x (8x8 phase-grid px) tile.
// out[b,co,2Y+r,2X+c] = m(b,co) * sum_{ci,tap} xs(b,ci,Y+dy,X+dx) * Wp
// ---------------------------------------------------------------------------
__global__ void __launch_bounds__(256) k_conv(const float* __restrict__ x,
                                              float* __restrict__ out) {
    const int phase = blockIdx.z;
    const int r = phase >> 1, c = phase & 1;
    const int b    = blockIdx.x >> 6;
    const int tile = blockIdx.x & 63;
    const int Y0 = (tile >> 3) * 8;
    const int X0 = (tile & 7) * 8;
    const int co0 = blockIdx.y * 128;

    const int tid = threadIdx.x;
    const int cog = tid >> 4;            // 0..15  -> 8 co each
    const int pxg = tid & 15;            // 0..15  -> 4 px each (row Yl, quad Xq)
    const int Yl = pxg >> 1;
    const int Xq = (pxg & 1) * 4;

    __shared__ float xs[16][10][12];     // [ci][y][x], x rows Y0-1..Y0+8, cols X0-1..X0+8
    __shared__ float ws[16][128];        // [ci][co]

    float acc[8][4];
#pragma unroll
    for (int i = 0; i < 8; ++i)
#pragma unroll
        for (int j = 0; j < 4; ++j) acc[i][j] = 0.f;

    for (int ch = 0; ch < CIN; ch += 16) {
        __syncthreads();
        // load x tile (modulated by s)
        for (int idx = tid; idx < 1600; idx += 256) {
            int k   = idx / 100;
            int rem = idx - k * 100;
            int yy  = rem / 10;
            int xx  = rem - yy * 10;
            int gy = Y0 - 1 + yy;
            int gx = X0 - 1 + xx;
            float v = 0.f;
            if ((unsigned)gy < 64u && (unsigned)gx < 64u)
                v = x[((b * CIN + ch + k) * HW + gy) * HW + gx] * g_s[b * CIN + ch + k];
            xs[k][yy][xx] = v;
        }

        for (int tap = 0; tap < 9; ++tap) {
            __syncthreads();
            const float* wg = g_wp + ((phase * 9 + tap) * CIN + ch) * COUT + co0;
            for (int idx = tid; idx < 2048; idx += 256) {
                int k  = idx >> 7;
                int co = idx & 127;
                ws[k][co] = wg[k * COUT + co];
            }
            __syncthreads();

            const int dyi = tap / 3;
            const int dxi = tap - dyi * 3;
            const int yrow = Yl + dyi;
            const int xcol = Xq + dxi;
#pragma unroll
            for (int k = 0; k < 16; ++k) {
                float xv[4];
#pragma unroll
                for (int j = 0; j < 4; ++j) xv[j] = xs[k][yrow][xcol + j];
#pragma unroll
                for (int i = 0; i < 8; ++i) {
                    float wv = ws[k][cog * 8 + i];
#pragma unroll
                    for (int j = 0; j < 4; ++j)
                        acc[i][j] = fmaf(wv, xv[j], acc[i][j]);
                }
            }
        }
    }

    // epilogue: multiply by scale*demod, write strided phase outputs
    const int Yg = Y0 + Yl;
    const int oy = 2 * Yg + r;
#pragma unroll
    for (int i = 0; i < 8; ++i) {
        int co = co0 + cog * 8 + i;
        float m = g_demod[b * COUT + co];
        float* op = out + ((size_t)(b * COUT + co) * 128 + oy) * 128;
#pragma unroll
        for (int j = 0; j < 4; ++j) {
            int ox = 2 * (X0 + Xq + j) + c;
            op[ox] = acc[i][j] * m;
        }
    }
}

// ---------------------------------------------------------------------------
extern "C" void kernel_launch(void* const* d_in, const int* in_sizes, int n_in,
                              void* d_out, int out_size) {
    const float* x          = (const float*)d_in[0];   // [8,512,64,64]
    const float* style      = (const float*)d_in[1];   // [8,512]
    const float* weight     = (const float*)d_in[2];   // [1,256,512,3,3]
    const float* mod_weight = (const float*)d_in[3];   // [512,512]
    const float* mod_bias   = (const float*)d_in[4];   // [512]
    float* out = (float*)d_out;                        // [8,256,128,128]

    k_style<<<512, 256>>>(style, mod_weight, mod_bias);
    k_wprep<<<512, 256>>>(weight);
    k_demod<<<256, 256>>>();
    dim3 grid(512, 2, 4);
    k_conv<<<grid, 256>>>(x, out);
}

// round 6
// speedup vs baseline: 6.7224x; 6.7163x over previous
#include <cuda_runtime.h>
#include <cuda_fp16.h>
#include <math.h>
#include <cstdint>

#define CIN   512
#define COUT  256
#define SDIM  512
#define NPIX  4356          // 66*66 zero-padded pixel grid per batch

// ---------------- device scratch ----------------
__device__ float g_s[8 * CIN];
__device__ float g_wsq[COUT * CIN];
__device__ float g_demod[8 * COUT];
__device__ __align__(16) __half g_xt[(size_t)8 * NPIX * CIN];        // 35.7 MB
__device__ __align__(16) __half g_wh[(size_t)4 * 9 * CIN * COUT];    // 9.4 MB

// ---------------- PTX helpers ----------------
__device__ __forceinline__ uint32_t smem_u32(const void* p) {
    uint32_t a;
    asm("{ .reg .u64 t; cvta.to.shared.u64 t, %1; cvt.u32.u64 %0, t; }" : "=r"(a) : "l"(p));
    return a;
}
__device__ __forceinline__ void cp16(uint32_t dst, const void* src) {
    asm volatile("cp.async.cg.shared.global [%0], [%1], 16;" :: "r"(dst), "l"(src));
}
#define CP_COMMIT() asm volatile("cp.async.commit_group;" ::: "memory")
#define CP_WAIT(n)  asm volatile("cp.async.wait_group %0;" :: "n"(n) : "memory")

#define LDSM4(r, a) asm volatile( \
    "ldmatrix.sync.aligned.m8n8.x4.shared.b16 {%0,%1,%2,%3},[%4];" \
    : "=r"((r)[0]),"=r"((r)[1]),"=r"((r)[2]),"=r"((r)[3]) : "r"(a))
#define LDSM4T(r, a) asm volatile( \
    "ldmatrix.sync.aligned.m8n8.x4.trans.shared.b16 {%0,%1,%2,%3},[%4];" \
    : "=r"((r)[0]),"=r"((r)[1]),"=r"((r)[2]),"=r"((r)[3]) : "r"(a))
#define MMA16816(d, a, b0, b1) asm volatile( \
    "mma.sync.aligned.m16n8k16.row.col.f32.f16.f16.f32 " \
    "{%0,%1,%2,%3},{%4,%5,%6,%7},{%8,%9},{%0,%1,%2,%3};" \
    : "+f"((d)[0]),"+f"((d)[1]),"+f"((d)[2]),"+f"((d)[3]) \
    : "r"((a)[0]),"r"((a)[1]),"r"((a)[2]),"r"((a)[3]), "r"(b0),"r"(b1))

// ---------------------------------------------------------------------------
__global__ void k_style(const float* __restrict__ style, const float* __restrict__ mw,
                        const float* __restrict__ mb) {
    int idx = blockIdx.x * 8 + (threadIdx.x >> 5);
    int lane = threadIdx.x & 31;
    int b = idx / CIN, ci = idx - b * CIN;
    const float* st = style + b * SDIM;
    const float* w = mw + ci * SDIM;
    float acc = 0.f;
    for (int d = lane; d < SDIM; d += 32) acc += st[d] * w[d];
#pragma unroll
    for (int o = 16; o; o >>= 1) acc += __shfl_xor_sync(0xffffffffu, acc, o);
    if (lane == 0) g_s[idx] = acc * 0.044194173824159216f + mb[ci];
}

__global__ void k_zero() {   // 8712 * 256 * 8 halves == 8 * 4356 * 512 exact
    size_t i = ((size_t)blockIdx.x * 256 + threadIdx.x) * 8;
    *(uint4*)(g_xt + i) = make_uint4(0, 0, 0, 0);
}

// transpose + modulate + fp16: Xt[b][(y+1)*66+(x+1)][ci]
__global__ void k_xt(const float* __restrict__ x) {
    __shared__ float xs[64][65];
    __shared__ float ss[64];
    int y = blockIdx.x, ch = blockIdx.y, b = blockIdx.z;
    int ci0 = ch * 64, tid = threadIdx.x;
    if (tid < 64) ss[tid] = g_s[b * CIN + ci0 + tid];
#pragma unroll
    for (int t = 0; t < 16; ++t) {
        int e = tid + t * 256;
        int ci = e >> 6, xx = e & 63;
        xs[ci][xx] = x[(((size_t)b * CIN + ci0 + ci) * 64 + y) * 64 + xx];
    }
    __syncthreads();
#pragma unroll
    for (int t = 0; t < 4; ++t) {
        int g = tid + t * 256;
        int xx = g >> 4, gl = g & 15;
        __half2 h0 = __floats2half2_rn(xs[gl*4+0][xx] * ss[gl*4+0], xs[gl*4+1][xx] * ss[gl*4+1]);
        __half2 h1 = __floats2half2_rn(xs[gl*4+2][xx] * ss[gl*4+2], xs[gl*4+3][xx] * ss[gl*4+3]);
        size_t pp = (size_t)(y + 1) * 66 + (xx + 1);
        __half2* d = (__half2*)(g_xt + ((size_t)b * NPIX + pp) * CIN + ci0 + gl * 4);
        d[0] = h0; d[1] = h1;
    }
}

// phase weights fp16: g_wh[((ph*9+tap)*512 + ci)*256 + co]
__global__ void k_wprep(const float* __restrict__ weight) {
    int idx = blockIdx.x * 256 + threadIdx.x;     // 32768
    int co = idx & 255, ci = (idx >> 8) * 4;
    float wv[4][3][3];
#pragma unroll
    for (int j = 0; j < 4; ++j) {
        float q = 0.f;
#pragma unroll
        for (int p = 0; p < 9; ++p) {
            float v = weight[((size_t)co * CIN + ci + j) * 9 + p];
            wv[j][p / 3][p % 3] = v;
            q += v * v;
        }
        g_wsq[co * CIN + ci + j] = q;
    }
    const float gv[4] = {0.25f, 0.75f, 0.75f, 0.25f};
#pragma unroll
    for (int ph = 0; ph < 4; ++ph) {
        int r = ph >> 1, c = ph & 1;
#pragma unroll
        for (int tap = 0; tap < 9; ++tap) {
            int a = 2 * (tap / 3) + 1 - r;
            int bb = 2 * (tap % 3) + 1 - c;
#pragma unroll
            for (int j = 0; j < 4; ++j) {
                float acc = 0.f;
#pragma unroll
                for (int p = 0; p < 3; ++p) {
                    int ia = a - 2 + p;
                    if (ia < 0 || ia > 3) continue;
#pragma unroll
                    for (int q = 0; q < 3; ++q) {
                        int ib = bb - 2 + q;
                        if (ib < 0 || ib > 3) continue;
                        acc += wv[j][p][q] * gv[ia] * gv[ib];
                    }
                }
                g_wh[((size_t)((ph * 9 + tap) * CIN) + ci + j) * COUT + co] = __float2half(acc);
            }
        }
    }
}

__global__ void k_demod() {
    int idx = blockIdx.x * 8 + (threadIdx.x >> 5);
    int lane = threadIdx.x & 31;
    int b = idx / COUT, co = idx - b * COUT;
    float acc = 0.f;
    for (int ci = lane; ci < CIN; ci += 32) {
        float sv = g_s[b * CIN + ci];
        acc += sv * sv * g_wsq[co * CIN + ci];
    }
#pragma unroll
    for (int o = 16; o; o >>= 1) acc += __shfl_xor_sync(0xffffffffu, acc, o);
    if (lane == 0)
        g_demod[idx] = 0.014731391274719738f * rsqrtf(2.1701388888888888e-4f * acc + 1e-8f);
}

// ---------------------------------------------------------------------------
// Main: CTA = 128px x 128co, K = 144 chunks x 32.  8 warps, warp tile 32px x 64co.
// grid: (32 mtiles, 2 cotiles, 32 = b*4+ph), 256 threads.
// ---------------------------------------------------------------------------
// smem geometry (bytes)
#define A_ROWH   40                    // halves per As row (32 + 8 pad)
#define B_ROWH   136                   // halves per Bs row (128 + 8 pad)
#define A_BUF    (128 * A_ROWH * 2)    // 10240 B per A buffer
#define B_BUF    (32 * B_ROWH * 2)     // 8704 B per B buffer

__global__ void __launch_bounds__(256) k_mma(float* __restrict__ out) {
    __shared__ __half As[2][128][A_ROWH];
    __shared__ __half Bs[2][32][B_ROWH];
    __shared__ float sd[128];

    const int tid = threadIdx.x, lane = tid & 31, wid = tid >> 5;
    const int mtile = blockIdx.x, cotile = blockIdx.y;
    const int b = blockIdx.z >> 2, ph = blockIdx.z & 3;
    const int mwarp = wid & 3, nwarp = wid >> 2;

    // A producer: thread t -> row t>>1 (2 threads/row), each 2x cp16 (32B)
    const int arow = tid >> 1;
    const int apx = mtile * 128 + arow;
    const int ay = apx >> 6, ax = apx & 63;
    const __half* aSrc = g_xt + ((size_t)b * NPIX + (size_t)(ay + 1) * 66 + ax + 1) * CIN
                       + (tid & 1) * 16;
    const uint32_t aDst = smem_u32(&As[0][arow][(tid & 1) * 16]);

    // B producer: thread t -> row t>>3 (8 threads/row), each 2x cp16 (seg and seg+8)
    const __half* bSrc = g_wh + ((size_t)(ph * 9) * CIN + (tid >> 3)) * COUT
                       + cotile * 128 + (tid & 7) * 8;
    const uint32_t bDst = smem_u32(&Bs[0][tid >> 3][(tid & 7) * 8]);

    // ldmatrix consumer base addresses (byte offsets into buffer 0)
    const uint32_t aLd = smem_u32(As)
        + (((lane & 7) + ((lane >> 3) & 1) * 8 + mwarp * 32) * A_ROWH + (lane >> 4) * 8) * 2;
    const uint32_t bLd = smem_u32(Bs)
        + ((((lane >> 3) & 1) * 8 + (lane & 7)) * B_ROWH + (lane >> 4) * 8 + nwarp * 64) * 2;

    float d[2][8][4];
#pragma unroll
    for (int i = 0; i < 2; ++i)
#pragma unroll
        for (int j = 0; j < 8; ++j)
#pragma unroll
            for (int k = 0; k < 4; ++k) d[i][j][k] = 0.f;

    auto load = [&](int j, int buf) {
        int tap = j >> 4, cic = j & 15;
        int tapd = (tap / 3 - 1) * 66 + (tap % 3) - 1;
        const __half* as = aSrc + (ptrdiff_t)tapd * CIN + cic * 32;
        uint32_t ad = aDst + buf * A_BUF;
        cp16(ad, as);
        cp16(ad + 16, as + 8);
        const __half* bs = bSrc + (size_t)(tap * CIN + cic * 32) * COUT;
        uint32_t bd = bDst + buf * B_BUF;
        cp16(bd, bs);
        cp16(bd + 128, bs + 64);      // second 64-co half of the row
    };

    load(0, 0);
    CP_COMMIT();

    for (int j = 0; j < 144; ++j) {
        const int buf = j & 1;
        if (j < 143) {
            load(j + 1, buf ^ 1);
            CP_COMMIT();
            CP_WAIT(1);
        } else {
            CP_WAIT(0);
        }
        __syncthreads();

#pragma unroll
        for (int ks = 0; ks < 2; ++ks) {
            uint32_t a[2][4];
#pragma unroll
            for (int mt = 0; mt < 2; ++mt)
                LDSM4(a[mt], aLd + buf * A_BUF + (mt * 16 * A_ROWH + ks * 16) * 2);
#pragma unroll
            for (int ng = 0; ng < 4; ++ng) {
                uint32_t bb[4];
                LDSM4T(bb, bLd + buf * B_BUF + (ks * 16 * B_ROWH + ng * 16) * 2);
#pragma unroll
                for (int mt = 0; mt < 2; ++mt) {
                    MMA16816(d[mt][ng * 2 + 0], a[mt], bb[0], bb[1]);
                    MMA16816(d[mt][ng * 2 + 1], a[mt], bb[2], bb[3]);
                }
            }
        }
        __syncthreads();
    }

    // epilogue
    if (tid < 128) sd[tid] = g_demod[b * COUT + cotile * 128 + tid];
    __syncthreads();

#pragma unroll
    for (int mt = 0; mt < 2; ++mt) {
        int pxb = mtile * 128 + mwarp * 32 + mt * 16 + (lane >> 2);
#pragma unroll
        for (int rr = 0; rr < 2; ++rr) {
            int px = pxb + rr * 8;
            int y = px >> 6, xx = px & 63;
            int oy = 2 * y + (ph >> 1), ox = 2 * xx + (ph & 1);
            float* ob = out + (((size_t)b * COUT + cotile * 128) * 128 + oy) * 128 + ox;
#pragma unroll
            for (int nt = 0; nt < 8; ++nt) {
                int col = nwarp * 64 + nt * 8 + (lane & 3) * 2;
                ob[(size_t)col * 16384]       = d[mt][nt][rr * 2 + 0] * sd[col];
                ob[(size_t)(col + 1) * 16384] = d[mt][nt][rr * 2 + 1] * sd[col + 1];
            }
        }
    }
}

// ---------------------------------------------------------------------------
extern "C" void kernel_launch(void* const* d_in, const int* in_sizes, int n_in,
                              void* d_out, int out_size) {
    const float* x          = (const float*)d_in[0];
    const float* style      = (const float*)d_in[1];
    const float* weight     = (const float*)d_in[2];
    const float* mod_weight = (const float*)d_in[3];
    const float* mod_bias   = (const float*)d_in[4];
    float* out = (float*)d_out;

    k_style<<<512, 256>>>(style, mod_weight, mod_bias);
    k_zero<<<8712, 256>>>();
    k_xt<<<dim3(64, 8, 8), 256>>>(x);
    k_wprep<<<128, 256>>>(weight);
    k_demod<<<256, 256>>>();
    k_mma<<<dim3(32, 2, 32), 256>>>(out);
}